// round 1
// baseline (speedup 1.0000x reference)
#include <cuda_runtime.h>
#include <math.h>

#define Bz 8
#define Lq 2048
#define Sk 1024
#define DM 1024
#define DLLM 4096
#define NH 16
#define DK 64
#define DHK 1024

// Scratch (allocation-free rule: __device__ globals)
__device__ float g_Q[(size_t)Bz * Lq * DHK];   // 64 MB
__device__ float g_K[(size_t)Bz * Sk * DHK];   // 32 MB
__device__ float g_V[(size_t)Bz * Sk * DHK];   // 32 MB
__device__ float g_C[(size_t)Bz * Lq * DHK];   // 64 MB

// ---------------------------------------------------------------------------
// SGEMM: C[M,N] = A[M,K] @ B[K,N] + bias[N]
// 128x128 block tile, K-tile 8, 256 threads, 8x8 per-thread micro-tile.
// All shapes here are multiples of 128/8 -> no bounds checks.
// ---------------------------------------------------------------------------
#define BM 128
#define BN 128
#define BK 8

__global__ __launch_bounds__(256) void sgemm_bias(
    const float* __restrict__ A, const float* __restrict__ B,
    const float* __restrict__ bias, float* __restrict__ C,
    int M, int N, int K)
{
    __shared__ float As[BK][BM];
    __shared__ float Bs[BK][BN];

    const int tid = threadIdx.x;
    const int tx = tid & 15;        // 0..15  (N direction)
    const int ty = tid >> 4;        // 0..15  (M direction)
    const int row0 = blockIdx.y * BM;
    const int col0 = blockIdx.x * BN;

    // load mapping: A tile 128x8 (float4 per thread x1), B tile 8x128
    const int arow = tid >> 1;            // 0..127
    const int acol = (tid & 1) * 4;       // 0 or 4
    const int brow = tid >> 5;            // 0..7
    const int bcol = (tid & 31) * 4;      // 0..124

    float acc[8][8];
#pragma unroll
    for (int i = 0; i < 8; i++)
#pragma unroll
        for (int j = 0; j < 8; j++) acc[i][j] = 0.f;

    const float* Aptr = A + (size_t)(row0 + arow) * K + acol;
    const float* Bptr = B + (size_t)brow * N + col0 + bcol;

    for (int k0 = 0; k0 < K; k0 += BK) {
        float4 a4 = *(const float4*)(Aptr + k0);
        As[acol + 0][arow] = a4.x;
        As[acol + 1][arow] = a4.y;
        As[acol + 2][arow] = a4.z;
        As[acol + 3][arow] = a4.w;
        float4 b4 = *(const float4*)(Bptr + (size_t)k0 * N);
        *(float4*)&Bs[brow][bcol] = b4;
        __syncthreads();

#pragma unroll
        for (int kk = 0; kk < BK; kk++) {
            float4 a0 = *(const float4*)&As[kk][ty * 8];
            float4 a1 = *(const float4*)&As[kk][ty * 8 + 4];
            float4 b0 = *(const float4*)&Bs[kk][tx * 8];
            float4 b1 = *(const float4*)&Bs[kk][tx * 8 + 4];
            float av[8] = {a0.x, a0.y, a0.z, a0.w, a1.x, a1.y, a1.z, a1.w};
            float bv[8] = {b0.x, b0.y, b0.z, b0.w, b1.x, b1.y, b1.z, b1.w};
#pragma unroll
            for (int i = 0; i < 8; i++)
#pragma unroll
                for (int j = 0; j < 8; j++)
                    acc[i][j] = fmaf(av[i], bv[j], acc[i][j]);
        }
        __syncthreads();
    }

#pragma unroll
    for (int i = 0; i < 8; i++) {
        const int r = row0 + ty * 8 + i;
#pragma unroll
        for (int j = 0; j < 8; j += 4) {
            const int c = col0 + tx * 8 + j;
            float4 o;
            o.x = acc[i][j + 0] + bias[c + 0];
            o.y = acc[i][j + 1] + bias[c + 1];
            o.z = acc[i][j + 2] + bias[c + 2];
            o.w = acc[i][j + 3] + bias[c + 3];
            *(float4*)(C + (size_t)r * N + c) = o;
        }
    }
}

// ---------------------------------------------------------------------------
// Fused flash-style attention.
// Grid: (L/64, H, B).  Block: 256 threads (16x16, 4x4 micro-tiles).
// Per block: 64 query rows x full E=64, looping S in tiles of 64 with
// online softmax. Shared tiles stored (e-major for Q/K) with pitch 68 so
// all operand reads are aligned LDS.128.
// ---------------------------------------------------------------------------
#define BQ 64
#define BS 64
#define PI 68   // shared pitch (floats): 68*4B = 272B, 16B-aligned rows

__global__ __launch_bounds__(256) void attn_kernel(
    const float* __restrict__ Q, const float* __restrict__ K,
    const float* __restrict__ V, float* __restrict__ O)
{
    extern __shared__ float sm[];
    float* Qs = sm;                    // [64][PI]  (e, q), pre-scaled
    float* Ks = Qs + 64 * PI;          // [64][PI]  (e, s)
    float* Vs = Ks + 64 * PI;          // [64][PI]  (s, e)
    float* Ps = Vs + 64 * PI;          // [64][PI]  (q, s) scores / probs
    float* row_m = Ps + 64 * PI;       // [64]
    float* row_l = row_m + 64;         // [64]
    float* row_f = row_l + 64;         // [64]

    const int tid = threadIdx.x;
    const int tx = tid & 15;
    const int ty = tid >> 4;
    const int q0 = blockIdx.x * BQ;
    const int h  = blockIdx.y;
    const int b  = blockIdx.z;
    const float scale = 0.125f;  // 1/sqrt(64)

    // Load Q tile transposed (e-major), pre-scaled.
    {
        const float* Qg = Q + (((size_t)b * Lq + q0) * NH + h) * DK;
        for (int i = tid; i < BQ * 16; i += 256) {
            const int q = i >> 4;
            const int e = (i & 15) * 4;
            float4 v = *(const float4*)(Qg + (size_t)q * DHK + e);
            Qs[(e + 0) * PI + q] = v.x * scale;
            Qs[(e + 1) * PI + q] = v.y * scale;
            Qs[(e + 2) * PI + q] = v.z * scale;
            Qs[(e + 3) * PI + q] = v.w * scale;
        }
    }
    if (tid < 64) { row_m[tid] = -INFINITY; row_l[tid] = 0.f; }

    float acc[4][4];
#pragma unroll
    for (int i = 0; i < 4; i++)
#pragma unroll
        for (int j = 0; j < 4; j++) acc[i][j] = 0.f;

    const float* Kg = K + (((size_t)b * Sk) * NH + h) * DK;
    const float* Vg = V + (((size_t)b * Sk) * NH + h) * DK;

    for (int s0 = 0; s0 < Sk; s0 += BS) {
        __syncthreads();  // prior-iter reads of Ks/Vs/Ps complete (and Q load on iter 0)
        // Load K (e-major) and V (s-major) tiles.
        for (int i = tid; i < BS * 16; i += 256) {
            const int s = i >> 4;
            const int e = (i & 15) * 4;
            float4 kv = *(const float4*)(Kg + (size_t)(s0 + s) * DHK + e);
            Ks[(e + 0) * PI + s] = kv.x;
            Ks[(e + 1) * PI + s] = kv.y;
            Ks[(e + 2) * PI + s] = kv.z;
            Ks[(e + 3) * PI + s] = kv.w;
            float4 vv = *(const float4*)(Vg + (size_t)(s0 + s) * DHK + e);
            *(float4*)&Vs[s * PI + e] = vv;
        }
        __syncthreads();

        // Scores: sc[i][j] = sum_e Qs[e][qi] * Ks[e][sj]
        float sc[4][4];
#pragma unroll
        for (int i = 0; i < 4; i++)
#pragma unroll
            for (int j = 0; j < 4; j++) sc[i][j] = 0.f;
#pragma unroll 8
        for (int e = 0; e < 64; e++) {
            float4 a = *(const float4*)&Qs[e * PI + ty * 4];
            float4 c = *(const float4*)&Ks[e * PI + tx * 4];
            float av[4] = {a.x, a.y, a.z, a.w};
            float cv[4] = {c.x, c.y, c.z, c.w};
#pragma unroll
            for (int i = 0; i < 4; i++)
#pragma unroll
                for (int j = 0; j < 4; j++)
                    sc[i][j] = fmaf(av[i], cv[j], sc[i][j]);
        }
#pragma unroll
        for (int i = 0; i < 4; i++) {
            float4 o = make_float4(sc[i][0], sc[i][1], sc[i][2], sc[i][3]);
            *(float4*)&Ps[(ty * 4 + i) * PI + tx * 4] = o;
        }
        __syncthreads();

        // Online softmax: 4 lanes per row.
        {
            const int r = tid >> 2;
            const int g = tid & 3;
            float* row = Ps + r * PI + g * 16;
            float mx = -INFINITY;
#pragma unroll
            for (int c = 0; c < 16; c++) mx = fmaxf(mx, row[c]);
            mx = fmaxf(mx, __shfl_xor_sync(0xffffffffu, mx, 1));
            mx = fmaxf(mx, __shfl_xor_sync(0xffffffffu, mx, 2));
            const float m_old = row_m[r];
            const float m_new = fmaxf(m_old, mx);
            float sum = 0.f;
#pragma unroll
            for (int c = 0; c < 16; c++) {
                float p = __expf(row[c] - m_new);
                row[c] = p;
                sum += p;
            }
            sum += __shfl_xor_sync(0xffffffffu, sum, 1);
            sum += __shfl_xor_sync(0xffffffffu, sum, 2);
            if (g == 0) {
                const float f = __expf(m_old - m_new);
                row_f[r] = f;
                row_l[r] = row_l[r] * f + sum;
                row_m[r] = m_new;
            }
        }
        __syncthreads();

        // Rescale accumulators + PV: acc[i][e] += P[qi][s] * Vs[s][e]
        {
            float f[4];
#pragma unroll
            for (int i = 0; i < 4; i++) f[i] = row_f[ty * 4 + i];
#pragma unroll
            for (int i = 0; i < 4; i++)
#pragma unroll
                for (int j = 0; j < 4; j++) acc[i][j] *= f[i];

#pragma unroll 4
            for (int j = 0; j < 64; j += 4) {
                float4 v0 = *(const float4*)&Vs[(j + 0) * PI + tx * 4];
                float4 v1 = *(const float4*)&Vs[(j + 1) * PI + tx * 4];
                float4 v2 = *(const float4*)&Vs[(j + 2) * PI + tx * 4];
                float4 v3 = *(const float4*)&Vs[(j + 3) * PI + tx * 4];
#pragma unroll
                for (int i = 0; i < 4; i++) {
                    float4 p = *(const float4*)&Ps[(ty * 4 + i) * PI + j];
                    acc[i][0] = fmaf(p.x, v0.x, acc[i][0]);
                    acc[i][1] = fmaf(p.x, v0.y, acc[i][1]);
                    acc[i][2] = fmaf(p.x, v0.z, acc[i][2]);
                    acc[i][3] = fmaf(p.x, v0.w, acc[i][3]);
                    acc[i][0] = fmaf(p.y, v1.x, acc[i][0]);
                    acc[i][1] = fmaf(p.y, v1.y, acc[i][1]);
                    acc[i][2] = fmaf(p.y, v1.z, acc[i][2]);
                    acc[i][3] = fmaf(p.y, v1.w, acc[i][3]);
                    acc[i][0] = fmaf(p.z, v2.x, acc[i][0]);
                    acc[i][1] = fmaf(p.z, v2.y, acc[i][1]);
                    acc[i][2] = fmaf(p.z, v2.z, acc[i][2]);
                    acc[i][3] = fmaf(p.z, v2.w, acc[i][3]);
                    acc[i][0] = fmaf(p.w, v3.x, acc[i][0]);
                    acc[i][1] = fmaf(p.w, v3.y, acc[i][1]);
                    acc[i][2] = fmaf(p.w, v3.z, acc[i][2]);
                    acc[i][3] = fmaf(p.w, v3.w, acc[i][3]);
                }
            }
        }
    }

    // Final normalize + store (row_l/row_f visible: last update preceded a sync).
    {
        float* Og = O + (((size_t)b * Lq + q0) * NH + h) * DK;
#pragma unroll
        for (int i = 0; i < 4; i++) {
            const float inv = 1.f / row_l[ty * 4 + i];
            float4 o = make_float4(acc[i][0] * inv, acc[i][1] * inv,
                                   acc[i][2] * inv, acc[i][3] * inv);
            *(float4*)(Og + (size_t)(ty * 4 + i) * DHK + tx * 4) = o;
        }
    }
}

// ---------------------------------------------------------------------------
// Launch
// ---------------------------------------------------------------------------
extern "C" void kernel_launch(void* const* d_in, const int* in_sizes, int n_in,
                              void* d_out, int out_size)
{
    const float* target = (const float*)d_in[0];   // [B,L,DM]
    const float* source = (const float*)d_in[1];   // [B,S,DLLM]
    const float* Wq = (const float*)d_in[2];
    const float* bq = (const float*)d_in[3];
    const float* Wk = (const float*)d_in[4];
    const float* bk = (const float*)d_in[5];
    const float* Wv = (const float*)d_in[6];
    const float* bv = (const float*)d_in[7];
    const float* Wo = (const float*)d_in[8];
    const float* bo = (const float*)d_in[9];
    float* out = (float*)d_out;

    float* Qb; cudaGetSymbolAddress((void**)&Qb, g_Q);
    float* Kb; cudaGetSymbolAddress((void**)&Kb, g_K);
    float* Vb; cudaGetSymbolAddress((void**)&Vb, g_V);
    float* Cb; cudaGetSymbolAddress((void**)&Cb, g_C);

    const int ML = Bz * Lq;   // 16384
    const int MS = Bz * Sk;   // 8192

    // Q = target @ Wq + bq
    sgemm_bias<<<dim3(DHK / BN, ML / BM), 256>>>(target, Wq, bq, Qb, ML, DHK, DM);
    // K = source @ Wk + bk ; V = source @ Wv + bv
    sgemm_bias<<<dim3(DHK / BN, MS / BM), 256>>>(source, Wk, bk, Kb, MS, DHK, DLLM);
    sgemm_bias<<<dim3(DHK / BN, MS / BM), 256>>>(source, Wv, bv, Vb, MS, DHK, DLLM);

    // Attention
    const int smem = (4 * 64 * PI + 3 * 64) * (int)sizeof(float);  // ~70 KB
    cudaFuncSetAttribute(attn_kernel, cudaFuncAttributeMaxDynamicSharedMemorySize, smem);
    attn_kernel<<<dim3(Lq / BQ, NH, Bz), 256, smem>>>(Qb, Kb, Vb, Cb);

    // out = C @ Wo + bo
    sgemm_bias<<<dim3(DLLM / BN, ML / BM), 256>>>(Cb, Wo, bo, out, ML, DLLM, DHK);
}

// round 5
// speedup vs baseline: 2.2104x; 2.2104x over previous
#include <cuda_runtime.h>
#include <cstdint>
#include <math.h>

#define Bz 8
#define Lq 2048
#define Sk 1024
#define DM 1024
#define DLLM 4096
#define NH 16
#define DK 64
#define DHK 1024

// Scratch (allocation-free rule: __device__ globals)
__device__ float g_Q[(size_t)Bz * Lq * DHK];    // 64 MB
__device__ float g_K[(size_t)Bz * Sk * DHK];    // 32 MB
__device__ float g_V[(size_t)Bz * Sk * DHK];    // 32 MB
__device__ float g_C[(size_t)Bz * Lq * DHK];    // 64 MB
__device__ float g_WT[(size_t)DLLM * DHK];      // 16 MB (transposed weight, reused)

// ===========================================================================
// Helpers
// ===========================================================================
__device__ __forceinline__ uint32_t smem_u32(const void* p) {
    uint32_t a;
    asm("{ .reg .u64 t; cvta.to.shared.u64 t, %1; cvt.u32.u64 %0, t; }" : "=r"(a) : "l"(p));
    return a;
}
__device__ __forceinline__ void cp16(uint32_t dst, const void* src) {
    asm volatile("cp.async.cg.shared.global [%0], [%1], 16;" :: "r"(dst), "l"(src));
}
#define CP_COMMIT() asm volatile("cp.async.commit_group;" ::: "memory")
#define CP_WAIT0()  asm volatile("cp.async.wait_group 0;" ::: "memory")

__device__ __forceinline__ uint32_t f2tf32(float x) {
    uint32_t r;
    asm("cvt.rna.tf32.f32 %0, %1;" : "=r"(r) : "f"(x));
    return r;
}
__device__ __forceinline__ void mma_tf32(float c[4], const uint32_t a[4], const uint32_t b[2]) {
    asm volatile(
        "mma.sync.aligned.m16n8k8.row.col.f32.tf32.tf32.f32 "
        "{%0,%1,%2,%3}, {%4,%5,%6,%7}, {%8,%9}, {%0,%1,%2,%3};"
        : "+f"(c[0]), "+f"(c[1]), "+f"(c[2]), "+f"(c[3])
        : "r"(a[0]), "r"(a[1]), "r"(a[2]), "r"(a[3]), "r"(b[0]), "r"(b[1]));
}

// ===========================================================================
// Weight transpose: in [R,C] row-major -> out [C,R] row-major
// ===========================================================================
__global__ __launch_bounds__(256) void transpose_k(
    const float* __restrict__ in, float* __restrict__ out, int R, int C)
{
    __shared__ float tile[32][33];
    const int c0 = blockIdx.x * 32, r0 = blockIdx.y * 32;
    const int x = threadIdx.x, y = threadIdx.y;  // 32 x 8
#pragma unroll
    for (int i = 0; i < 32; i += 8)
        tile[y + i][x] = in[(size_t)(r0 + y + i) * C + c0 + x];
    __syncthreads();
#pragma unroll
    for (int i = 0; i < 32; i += 8)
        out[(size_t)(c0 + y + i) * R + r0 + x] = tile[x][y + i];
}

// ===========================================================================
// tf32 mma.sync GEMM: C[M,N] = A[M,K] @ Bt[N,K]^T + bias
// 128x128x32 block tile, 8 warps (2M x 4N), 64x32 warp tile, m16n8k8 MMA.
// Tiles in smem as [row][k] with stride 36 floats (conflict-free fragments).
// Double-buffered cp.async.  grid = (N/128, M/128), 256 threads.
// ===========================================================================
#define GM 128
#define GN 128
#define GKC 32
#define TST 36                                   // tile k-stride in floats
#define STAGE_FLOATS (2 * 128 * TST)             // A tile + B tile = 9216
#define SMEM_GEMM (2 * STAGE_FLOATS * 4)         // 73728 bytes

__global__ __launch_bounds__(256, 2) void gemm_mma(
    const float* __restrict__ A, const float* __restrict__ Bt,
    const float* __restrict__ bias, float* __restrict__ C,
    int K, int N)
{
    extern __shared__ float smf[];
    const uint32_t smem_base = smem_u32(smf);
    const int tid  = threadIdx.x;
    const int wid  = tid >> 5;
    const int lane = tid & 31;
    const int wm   = wid >> 2;          // 0..1  (M)
    const int wn   = wid & 3;           // 0..3  (N)
    const int gid  = lane >> 2;         // groupID 0..7
    const int tig  = lane & 3;          // threadID-in-group 0..3
    const int m0 = blockIdx.y * GM;
    const int n0 = blockIdx.x * GN;

    // cp.async granule mapping: g in [0,1024): row = g>>3, c4 = g&7
    const int grow = tid >> 1;                  // reshaped: 4 granules/thread
    // We use: granule g = tid + u*256, u = 0..3 for A, same for B.

    const float* Ag = A + (size_t)m0 * K;
    const float* Bg = Bt + (size_t)n0 * K;

    auto issue_stage = [&](int i) {
        const int k0 = i * GKC;
        const uint32_t sb = smem_base + (uint32_t)((i & 1) * STAGE_FLOATS * 4);
#pragma unroll
        for (int u = 0; u < 4; u++) {
            const int g = tid + u * 256;
            const int row = g >> 3, c4 = g & 7;
            cp16(sb + (uint32_t)(row * TST * 4 + c4 * 16),
                 Ag + (size_t)row * K + k0 + c4 * 4);
        }
        const uint32_t sbB = smem_base + (uint32_t)((i & 1) * STAGE_FLOATS * 4 + 128 * TST * 4);
#pragma unroll
        for (int u = 0; u < 4; u++) {
            const int g = tid + u * 256;
            const int row = g >> 3, c4 = g & 7;
            cp16(sbB + (uint32_t)(row * TST * 4 + c4 * 16),
                 Bg + (size_t)row * K + k0 + c4 * 4);
        }
        CP_COMMIT();
    };
    (void)grow;

    float acc[4][4][4];
#pragma unroll
    for (int mt = 0; mt < 4; mt++)
#pragma unroll
        for (int nt = 0; nt < 4; nt++)
#pragma unroll
            for (int r = 0; r < 4; r++) acc[mt][nt][r] = 0.f;

    const int niter = K / GKC;
    issue_stage(0);

    for (int i = 0; i < niter; i++) {
        CP_WAIT0();
        __syncthreads();
        if (i + 1 < niter) issue_stage(i + 1);

        const float* As = smf + (i & 1) * STAGE_FLOATS;
        const float* Bs = As + 128 * TST;

#pragma unroll
        for (int ks = 0; ks < 4; ks++) {
            const int k0 = ks * 8;
            uint32_t af[4][4];
#pragma unroll
            for (int mt = 0; mt < 4; mt++) {
                const float* pa = As + (wm * 64 + mt * 16 + gid) * TST + k0 + tig;
                af[mt][0] = f2tf32(pa[0]);
                af[mt][1] = f2tf32(pa[8 * TST]);
                af[mt][2] = f2tf32(pa[4]);
                af[mt][3] = f2tf32(pa[8 * TST + 4]);
            }
            uint32_t bf[4][2];
#pragma unroll
            for (int nt = 0; nt < 4; nt++) {
                const float* pb = Bs + (wn * 32 + nt * 8 + gid) * TST + k0 + tig;
                bf[nt][0] = f2tf32(pb[0]);
                bf[nt][1] = f2tf32(pb[4]);
            }
#pragma unroll
            for (int mt = 0; mt < 4; mt++)
#pragma unroll
                for (int nt = 0; nt < 4; nt++)
                    mma_tf32(acc[mt][nt], af[mt], bf[nt]);
        }
        __syncthreads();
    }

    // Epilogue: c0/c1 at (row=gid, col=2*tig[+1]), c2/c3 at row=gid+8.
#pragma unroll
    for (int mt = 0; mt < 4; mt++) {
        const int r = m0 + wm * 64 + mt * 16 + gid;
#pragma unroll
        for (int nt = 0; nt < 4; nt++) {
            const int c = n0 + wn * 32 + nt * 8 + tig * 2;
            const float bx = bias[c], by = bias[c + 1];
            float2 o0 = make_float2(acc[mt][nt][0] + bx, acc[mt][nt][1] + by);
            float2 o1 = make_float2(acc[mt][nt][2] + bx, acc[mt][nt][3] + by);
            *(float2*)(C + (size_t)r * N + c) = o0;
            *(float2*)(C + (size_t)(r + 8) * N + c) = o1;
        }
    }
}

// ===========================================================================
// Fused flash-style attention (unchanged — correct, fma-bound)
// ===========================================================================
#define BQ 64
#define BS 64
#define PI 68

__global__ __launch_bounds__(256) void attn_kernel(
    const float* __restrict__ Q, const float* __restrict__ K,
    const float* __restrict__ V, float* __restrict__ O)
{
    extern __shared__ float sm[];
    float* Qs = sm;
    float* Ks = Qs + 64 * PI;
    float* Vs = Ks + 64 * PI;
    float* Ps = Vs + 64 * PI;
    float* row_m = Ps + 64 * PI;
    float* row_l = row_m + 64;
    float* row_f = row_l + 64;

    const int tid = threadIdx.x;
    const int tx = tid & 15;
    const int ty = tid >> 4;
    const int q0 = blockIdx.x * BQ;
    const int h  = blockIdx.y;
    const int b  = blockIdx.z;
    const float scale = 0.125f;

    {
        const float* Qg = Q + (((size_t)b * Lq + q0) * NH + h) * DK;
        for (int i = tid; i < BQ * 16; i += 256) {
            const int q = i >> 4;
            const int e = (i & 15) * 4;
            float4 v = *(const float4*)(Qg + (size_t)q * DHK + e);
            Qs[(e + 0) * PI + q] = v.x * scale;
            Qs[(e + 1) * PI + q] = v.y * scale;
            Qs[(e + 2) * PI + q] = v.z * scale;
            Qs[(e + 3) * PI + q] = v.w * scale;
        }
    }
    if (tid < 64) { row_m[tid] = -INFINITY; row_l[tid] = 0.f; }

    float acc[4][4];
#pragma unroll
    for (int i = 0; i < 4; i++)
#pragma unroll
        for (int j = 0; j < 4; j++) acc[i][j] = 0.f;

    const float* Kg = K + (((size_t)b * Sk) * NH + h) * DK;
    const float* Vg = V + (((size_t)b * Sk) * NH + h) * DK;

    for (int s0 = 0; s0 < Sk; s0 += BS) {
        __syncthreads();
        for (int i = tid; i < BS * 16; i += 256) {
            const int s = i >> 4;
            const int e = (i & 15) * 4;
            float4 kv = *(const float4*)(Kg + (size_t)(s0 + s) * DHK + e);
            Ks[(e + 0) * PI + s] = kv.x;
            Ks[(e + 1) * PI + s] = kv.y;
            Ks[(e + 2) * PI + s] = kv.z;
            Ks[(e + 3) * PI + s] = kv.w;
            float4 vv = *(const float4*)(Vg + (size_t)(s0 + s) * DHK + e);
            *(float4*)&Vs[s * PI + e] = vv;
        }
        __syncthreads();

        float sc[4][4];
#pragma unroll
        for (int i = 0; i < 4; i++)
#pragma unroll
            for (int j = 0; j < 4; j++) sc[i][j] = 0.f;
#pragma unroll 8
        for (int e = 0; e < 64; e++) {
            float4 a = *(const float4*)&Qs[e * PI + ty * 4];
            float4 c = *(const float4*)&Ks[e * PI + tx * 4];
            float av[4] = {a.x, a.y, a.z, a.w};
            float cv[4] = {c.x, c.y, c.z, c.w};
#pragma unroll
            for (int i = 0; i < 4; i++)
#pragma unroll
                for (int j = 0; j < 4; j++)
                    sc[i][j] = fmaf(av[i], cv[j], sc[i][j]);
        }
#pragma unroll
        for (int i = 0; i < 4; i++) {
            float4 o = make_float4(sc[i][0], sc[i][1], sc[i][2], sc[i][3]);
            *(float4*)&Ps[(ty * 4 + i) * PI + tx * 4] = o;
        }
        __syncthreads();

        {
            const int r = tid >> 2;
            const int g = tid & 3;
            float* row = Ps + r * PI + g * 16;
            float mx = -INFINITY;
#pragma unroll
            for (int c = 0; c < 16; c++) mx = fmaxf(mx, row[c]);
            mx = fmaxf(mx, __shfl_xor_sync(0xffffffffu, mx, 1));
            mx = fmaxf(mx, __shfl_xor_sync(0xffffffffu, mx, 2));
            const float m_old = row_m[r];
            const float m_new = fmaxf(m_old, mx);
            float sum = 0.f;
#pragma unroll
            for (int c = 0; c < 16; c++) {
                float p = __expf(row[c] - m_new);
                row[c] = p;
                sum += p;
            }
            sum += __shfl_xor_sync(0xffffffffu, sum, 1);
            sum += __shfl_xor_sync(0xffffffffu, sum, 2);
            if (g == 0) {
                const float f = __expf(m_old - m_new);
                row_f[r] = f;
                row_l[r] = row_l[r] * f + sum;
                row_m[r] = m_new;
            }
        }
        __syncthreads();

        {
            float f[4];
#pragma unroll
            for (int i = 0; i < 4; i++) f[i] = row_f[ty * 4 + i];
#pragma unroll
            for (int i = 0; i < 4; i++)
#pragma unroll
                for (int j = 0; j < 4; j++) acc[i][j] *= f[i];

#pragma unroll 4
            for (int j = 0; j < 64; j += 4) {
                float4 v0 = *(const float4*)&Vs[(j + 0) * PI + tx * 4];
                float4 v1 = *(const float4*)&Vs[(j + 1) * PI + tx * 4];
                float4 v2 = *(const float4*)&Vs[(j + 2) * PI + tx * 4];
                float4 v3 = *(const float4*)&Vs[(j + 3) * PI + tx * 4];
#pragma unroll
                for (int i = 0; i < 4; i++) {
                    float4 p = *(const float4*)&Ps[(ty * 4 + i) * PI + j];
                    acc[i][0] = fmaf(p.x, v0.x, acc[i][0]);
                    acc[i][1] = fmaf(p.x, v0.y, acc[i][1]);
                    acc[i][2] = fmaf(p.x, v0.z, acc[i][2]);
                    acc[i][3] = fmaf(p.x, v0.w, acc[i][3]);
                    acc[i][0] = fmaf(p.y, v1.x, acc[i][0]);
                    acc[i][1] = fmaf(p.y, v1.y, acc[i][1]);
                    acc[i][2] = fmaf(p.y, v1.z, acc[i][2]);
                    acc[i][3] = fmaf(p.y, v1.w, acc[i][3]);
                    acc[i][0] = fmaf(p.z, v2.x, acc[i][0]);
                    acc[i][1] = fmaf(p.z, v2.y, acc[i][1]);
                    acc[i][2] = fmaf(p.z, v2.z, acc[i][2]);
                    acc[i][3] = fmaf(p.z, v2.w, acc[i][3]);
                    acc[i][0] = fmaf(p.w, v3.x, acc[i][0]);
                    acc[i][1] = fmaf(p.w, v3.y, acc[i][1]);
                    acc[i][2] = fmaf(p.w, v3.z, acc[i][2]);
                    acc[i][3] = fmaf(p.w, v3.w, acc[i][3]);
                }
            }
        }
    }

    {
        float* Og = O + (((size_t)b * Lq + q0) * NH + h) * DK;
#pragma unroll
        for (int i = 0; i < 4; i++) {
            const float inv = 1.f / row_l[ty * 4 + i];
            float4 o = make_float4(acc[i][0] * inv, acc[i][1] * inv,
                                   acc[i][2] * inv, acc[i][3] * inv);
            *(float4*)(Og + (size_t)(ty * 4 + i) * DHK + tx * 4) = o;
        }
    }
}

// ===========================================================================
// Launch
// ===========================================================================
extern "C" void kernel_launch(void* const* d_in, const int* in_sizes, int n_in,
                              void* d_out, int out_size)
{
    const float* target = (const float*)d_in[0];
    const float* source = (const float*)d_in[1];
    const float* Wq = (const float*)d_in[2];
    const float* bq = (const float*)d_in[3];
    const float* Wk = (const float*)d_in[4];
    const float* bk = (const float*)d_in[5];
    const float* Wv = (const float*)d_in[6];
    const float* bv = (const float*)d_in[7];
    const float* Wo = (const float*)d_in[8];
    const float* bo = (const float*)d_in[9];
    float* out = (float*)d_out;

    float* Qb; cudaGetSymbolAddress((void**)&Qb, g_Q);
    float* Kb; cudaGetSymbolAddress((void**)&Kb, g_K);
    float* Vb; cudaGetSymbolAddress((void**)&Vb, g_V);
    float* Cb; cudaGetSymbolAddress((void**)&Cb, g_C);
    float* WT; cudaGetSymbolAddress((void**)&WT, g_WT);

    const int ML = Bz * Lq;   // 16384
    const int MS = Bz * Sk;   // 8192
    const int asmem = (4 * 64 * PI + 3 * 64) * (int)sizeof(float);

    cudaFuncSetAttribute(gemm_mma, cudaFuncAttributeMaxDynamicSharedMemorySize, SMEM_GEMM);
    cudaFuncSetAttribute(attn_kernel, cudaFuncAttributeMaxDynamicSharedMemorySize, asmem);

    // Q = target @ Wq + bq    (Wq [DM, DHK] -> WT [DHK, DM])
    transpose_k<<<dim3(DHK / 32, DM / 32), dim3(32, 8)>>>(Wq, WT, DM, DHK);
    gemm_mma<<<dim3(DHK / GN, ML / GM), 256, SMEM_GEMM>>>(target, WT, bq, Qb, DM, DHK);

    // K = source @ Wk + bk    (Wk [DLLM, DHK] -> WT [DHK, DLLM])
    transpose_k<<<dim3(DHK / 32, DLLM / 32), dim3(32, 8)>>>(Wk, WT, DLLM, DHK);
    gemm_mma<<<dim3(DHK / GN, MS / GM), 256, SMEM_GEMM>>>(source, WT, bk, Kb, DLLM, DHK);

    // V = source @ Wv + bv
    transpose_k<<<dim3(DHK / 32, DLLM / 32), dim3(32, 8)>>>(Wv, WT, DLLM, DHK);
    gemm_mma<<<dim3(DHK / GN, MS / GM), 256, SMEM_GEMM>>>(source, WT, bv, Vb, DLLM, DHK);

    // Attention
    attn_kernel<<<dim3(Lq / BQ, NH, Bz), 256, asmem>>>(Qb, Kb, Vb, Cb);

    // out = C @ Wo + bo       (Wo [DHK, DLLM] -> WT [DLLM, DHK])
    transpose_k<<<dim3(DLLM / 32, DHK / 32), dim3(32, 8)>>>(Wo, WT, DHK, DLLM);
    gemm_mma<<<dim3(DLLM / GN, ML / GM), 256, SMEM_GEMM>>>(Cb, WT, bo, out, DHK, DLLM);
}

// round 8
// speedup vs baseline: 3.4941x; 1.5807x over previous
#include <cuda_runtime.h>
#include <cstdint>
#include <math.h>

#define Bz 8
#define Lq 2048
#define Sk 1024
#define DM 1024
#define DLLM 4096
#define NH 16
#define DK 64
#define DHK 1024

// Scratch (allocation-free rule: __device__ globals)
__device__ float g_Q[(size_t)Bz * Lq * DHK];    // 64 MB
__device__ float g_K[(size_t)Bz * Sk * DHK];    // 32 MB
__device__ float g_V[(size_t)Bz * Sk * DHK];    // 32 MB
__device__ float g_C[(size_t)Bz * Lq * DHK];    // 64 MB (rounded target, then attn out)
__device__ float g_WT[(size_t)DLLM * DHK];      // 16 MB (transposed+rounded weight)
__device__ float g_Sr[(size_t)Bz * Sk * DLLM];  // 128 MB (rounded source)

// ===========================================================================
// Helpers
// ===========================================================================
__device__ __forceinline__ uint32_t smem_u32(const void* p) {
    uint32_t a;
    asm("{ .reg .u64 t; cvta.to.shared.u64 t, %1; cvt.u32.u64 %0, t; }" : "=r"(a) : "l"(p));
    return a;
}
__device__ __forceinline__ void cp16(uint32_t dst, const void* src) {
    asm volatile("cp.async.cg.shared.global [%0], [%1], 16;" :: "r"(dst), "l"(src));
}
#define CP_COMMIT() asm volatile("cp.async.commit_group;" ::: "memory")
#define CP_WAIT0()  asm volatile("cp.async.wait_group 0;" ::: "memory")

__device__ __forceinline__ float rnd_tf32(float x) {
    uint32_t r;
    asm("cvt.rna.tf32.f32 %0, %1;" : "=r"(r) : "f"(x));
    return __uint_as_float(r);
}
__device__ __forceinline__ void mma_tf32(float c[4], const uint32_t a[4], const uint32_t b[2]) {
    asm volatile(
        "mma.sync.aligned.m16n8k8.row.col.f32.tf32.tf32.f32 "
        "{%0,%1,%2,%3}, {%4,%5,%6,%7}, {%8,%9}, {%0,%1,%2,%3};"
        : "+f"(c[0]), "+f"(c[1]), "+f"(c[2]), "+f"(c[3])
        : "r"(a[0]), "r"(a[1]), "r"(a[2]), "r"(a[3]), "r"(b[0]), "r"(b[1]));
}

// ===========================================================================
// Elementwise tf32 rounding pre-pass (float4 vectorized, sizes divisible)
// ===========================================================================
__global__ __launch_bounds__(256) void round_tf32_k(
    const float4* __restrict__ in, float4* __restrict__ out, int n4)
{
    const int i = blockIdx.x * 256 + threadIdx.x;
    if (i < n4) {
        float4 v = in[i];
        v.x = rnd_tf32(v.x); v.y = rnd_tf32(v.y);
        v.z = rnd_tf32(v.z); v.w = rnd_tf32(v.w);
        out[i] = v;
    }
}

// ===========================================================================
// Weight transpose + tf32 round: in [R,C] row-major -> out [C,R] row-major
// ===========================================================================
__global__ __launch_bounds__(256) void transpose_k(
    const float* __restrict__ in, float* __restrict__ out, int R, int C)
{
    __shared__ float tile[32][33];
    const int c0 = blockIdx.x * 32, r0 = blockIdx.y * 32;
    const int x = threadIdx.x, y = threadIdx.y;  // 32 x 8
#pragma unroll
    for (int i = 0; i < 32; i += 8)
        tile[y + i][x] = in[(size_t)(r0 + y + i) * C + c0 + x];
    __syncthreads();
#pragma unroll
    for (int i = 0; i < 32; i += 8)
        out[(size_t)(c0 + y + i) * R + r0 + x] = rnd_tf32(tile[x][y + i]);
}

// ===========================================================================
// tf32 mma.sync GEMM: C[M,N] = A[M,K] @ Bt[N,K]^T + bias
// Inputs pre-rounded to tf32 -> inner loop is pure LDS + HMMA.
// 128x128x32 block tile, 8 warps (2M x 4N), m16n8k8, double-buffered cp.async.
// RND: round outputs to tf32 (for tensors that feed later tf32 GEMMs).
// ===========================================================================
#define GM 128
#define GN 128
#define GKC 32
#define TST 36
#define STAGE_FLOATS (2 * 128 * TST)
#define SMEM_GEMM (2 * STAGE_FLOATS * 4)         // 73728 bytes

template <int RND>
__global__ __launch_bounds__(256, 2) void gemm_mma(
    const float* __restrict__ A, const float* __restrict__ Bt,
    const float* __restrict__ bias, float* __restrict__ C,
    int K, int N)
{
    extern __shared__ float smf[];
    const uint32_t smem_base = smem_u32(smf);
    const int tid  = threadIdx.x;
    const int wid  = tid >> 5;
    const int lane = tid & 31;
    const int wm   = wid >> 2;
    const int wn   = wid & 3;
    const int gid  = lane >> 2;
    const int tig  = lane & 3;
    const int m0 = blockIdx.y * GM;
    const int n0 = blockIdx.x * GN;

    const float* Ag = A + (size_t)m0 * K;
    const float* Bg = Bt + (size_t)n0 * K;

    auto issue_stage = [&](int i) {
        const int k0 = i * GKC;
        const uint32_t sb = smem_base + (uint32_t)((i & 1) * STAGE_FLOATS * 4);
#pragma unroll
        for (int u = 0; u < 4; u++) {
            const int g = tid + u * 256;
            const int row = g >> 3, c4 = g & 7;
            cp16(sb + (uint32_t)(row * TST * 4 + c4 * 16),
                 Ag + (size_t)row * K + k0 + c4 * 4);
        }
        const uint32_t sbB = sb + 128 * TST * 4;
#pragma unroll
        for (int u = 0; u < 4; u++) {
            const int g = tid + u * 256;
            const int row = g >> 3, c4 = g & 7;
            cp16(sbB + (uint32_t)(row * TST * 4 + c4 * 16),
                 Bg + (size_t)row * K + k0 + c4 * 4);
        }
        CP_COMMIT();
    };

    float acc[4][4][4];
#pragma unroll
    for (int mt = 0; mt < 4; mt++)
#pragma unroll
        for (int nt = 0; nt < 4; nt++)
#pragma unroll
            for (int r = 0; r < 4; r++) acc[mt][nt][r] = 0.f;

    const int niter = K / GKC;
    issue_stage(0);

    for (int i = 0; i < niter; i++) {
        CP_WAIT0();
        __syncthreads();
        if (i + 1 < niter) issue_stage(i + 1);

        const uint32_t* As = (const uint32_t*)(smf + (i & 1) * STAGE_FLOATS);
        const uint32_t* Bs = As + 128 * TST;

#pragma unroll
        for (int ks = 0; ks < 4; ks++) {
            const int k0 = ks * 8;
            uint32_t af[4][4];
#pragma unroll
            for (int mt = 0; mt < 4; mt++) {
                const uint32_t* pa = As + (wm * 64 + mt * 16 + gid) * TST + k0 + tig;
                af[mt][0] = pa[0];
                af[mt][1] = pa[8 * TST];
                af[mt][2] = pa[4];
                af[mt][3] = pa[8 * TST + 4];
            }
            uint32_t bf[4][2];
#pragma unroll
            for (int nt = 0; nt < 4; nt++) {
                const uint32_t* pb = Bs + (wn * 32 + nt * 8 + gid) * TST + k0 + tig;
                bf[nt][0] = pb[0];
                bf[nt][1] = pb[4];
            }
#pragma unroll
            for (int mt = 0; mt < 4; mt++)
#pragma unroll
                for (int nt = 0; nt < 4; nt++)
                    mma_tf32(acc[mt][nt], af[mt], bf[nt]);
        }
        __syncthreads();
    }

#pragma unroll
    for (int mt = 0; mt < 4; mt++) {
        const int r = m0 + wm * 64 + mt * 16 + gid;
#pragma unroll
        for (int nt = 0; nt < 4; nt++) {
            const int c = n0 + wn * 32 + nt * 8 + tig * 2;
            const float bx = bias[c], by = bias[c + 1];
            float2 o0, o1;
            o0.x = acc[mt][nt][0] + bx; o0.y = acc[mt][nt][1] + by;
            o1.x = acc[mt][nt][2] + bx; o1.y = acc[mt][nt][3] + by;
            if (RND) {
                o0.x = rnd_tf32(o0.x); o0.y = rnd_tf32(o0.y);
                o1.x = rnd_tf32(o1.x); o1.y = rnd_tf32(o1.y);
            }
            *(float2*)(C + (size_t)r * N + c) = o0;
            *(float2*)(C + (size_t)(r + 8) * N + c) = o1;
        }
    }
}

// ===========================================================================
// Tensor-core flash attention (tf32 mma.sync).
// Grid (L/64, H, B), 128 threads (4 warps). Warp w owns q-rows [16w,16w+16).
// Smem layout (dynamic, 53248 B):
//   Qs [64][68]  — Q tile; aliased as Ps after Q fragments move to registers
//   Ks [64][68]  — K tile [s][e]; stride 68 => QK^T B-frags conflict-free
//   Vs [64][72]  — V tile [s][e]; stride 72 => PV B-frags conflict-free
// ===========================================================================
#define QK_ST 68
#define V_ST  72
#define ATTN_SMEM ((2 * 64 * QK_ST + 64 * V_ST) * 4)   // 53248 bytes

__global__ __launch_bounds__(128) void attn_tc(
    const float* __restrict__ Q, const float* __restrict__ K,
    const float* __restrict__ V, float* __restrict__ O)
{
    extern __shared__ float sm[];
    float* Qs = sm;                        // [64][QK_ST]
    float* Ks = Qs + 64 * QK_ST;           // [64][QK_ST]
    float* Vs = Ks + 64 * QK_ST;           // [64][V_ST]
    float* Ps = Qs;                        // alias (Q is register-resident in loop)

    const int tid  = threadIdx.x;
    const int wid  = tid >> 5;
    const int lane = tid & 31;
    const int gid  = lane >> 2;
    const int tig  = lane & 3;
    const int q0 = blockIdx.x * 64;
    const int h  = blockIdx.y;
    const int b  = blockIdx.z;

    const float* Qg = Q + ((size_t)b * Lq + q0) * DHK + h * DK;
    const float* Kg = K + ((size_t)b * Sk) * DHK + h * DK;
    const float* Vg = V + ((size_t)b * Sk) * DHK + h * DK;

    // Load Q tile [64 q][64 e]
    for (int g = tid; g < 64 * 16; g += 128) {
        const int r = g >> 4, e4 = g & 15;
        float4 v = *(const float4*)(Qg + (size_t)r * DHK + e4 * 4);
        *(float4*)&Qs[r * QK_ST + e4 * 4] = v;
    }
    __syncthreads();

    // Q fragments to registers, pre-scaled by 1/8 (power of 2: tf32-exact)
    const int r0 = wid * 16 + gid;
    uint32_t qf[8][4];
#pragma unroll
    for (int k0 = 0; k0 < 8; k0++) {
        qf[k0][0] = __float_as_uint(Qs[r0 * QK_ST + k0 * 8 + tig] * 0.125f);
        qf[k0][1] = __float_as_uint(Qs[(r0 + 8) * QK_ST + k0 * 8 + tig] * 0.125f);
        qf[k0][2] = __float_as_uint(Qs[r0 * QK_ST + k0 * 8 + tig + 4] * 0.125f);
        qf[k0][3] = __float_as_uint(Qs[(r0 + 8) * QK_ST + k0 * 8 + tig + 4] * 0.125f);
    }

    float m0 = -INFINITY, m1 = -INFINITY, l0 = 0.f, l1 = 0.f;
    float acc[8][4];
#pragma unroll
    for (int nt = 0; nt < 8; nt++)
#pragma unroll
        for (int r = 0; r < 4; r++) acc[nt][r] = 0.f;

    for (int s0 = 0; s0 < Sk; s0 += 64) {
        __syncthreads();  // prior-iter Ks/Vs/Ps reads done; Q frags loaded (iter 0)
        for (int g = tid; g < 64 * 16; g += 128) {
            const int r = g >> 4, e4 = g & 15;
            float4 kv = *(const float4*)(Kg + (size_t)(s0 + r) * DHK + e4 * 4);
            *(float4*)&Ks[r * QK_ST + e4 * 4] = kv;
            float4 vv = *(const float4*)(Vg + (size_t)(s0 + r) * DHK + e4 * 4);
            *(float4*)&Vs[r * V_ST + e4 * 4] = vv;
        }
        __syncthreads();

        // Scores: sc[nt] covers cols nt*8 + {2tig, 2tig+1}, rows r0 / r0+8
        float sc[8][4];
#pragma unroll
        for (int nt = 0; nt < 8; nt++)
#pragma unroll
            for (int r = 0; r < 4; r++) sc[nt][r] = 0.f;
#pragma unroll
        for (int k0 = 0; k0 < 8; k0++) {
#pragma unroll
            for (int nt = 0; nt < 8; nt++) {
                const uint32_t* pk =
                    (const uint32_t*)Ks + (nt * 8 + gid) * QK_ST + k0 * 8 + tig;
                uint32_t bf[2] = {pk[0], pk[4]};
                mma_tf32(sc[nt], qf[k0], bf);
            }
        }

        // Register softmax (rows r0, r0+8; each row spread over 4 tig lanes)
        float mx0 = -INFINITY, mx1 = -INFINITY;
#pragma unroll
        for (int nt = 0; nt < 8; nt++) {
            mx0 = fmaxf(mx0, fmaxf(sc[nt][0], sc[nt][1]));
            mx1 = fmaxf(mx1, fmaxf(sc[nt][2], sc[nt][3]));
        }
        mx0 = fmaxf(mx0, __shfl_xor_sync(0xffffffffu, mx0, 1));
        mx0 = fmaxf(mx0, __shfl_xor_sync(0xffffffffu, mx0, 2));
        mx1 = fmaxf(mx1, __shfl_xor_sync(0xffffffffu, mx1, 1));
        mx1 = fmaxf(mx1, __shfl_xor_sync(0xffffffffu, mx1, 2));
        const float mn0 = fmaxf(m0, mx0), mn1 = fmaxf(m1, mx1);
        const float f0 = __expf(m0 - mn0), f1 = __expf(m1 - mn1);
        float sum0 = 0.f, sum1 = 0.f;
#pragma unroll
        for (int nt = 0; nt < 8; nt++) {
            sc[nt][0] = __expf(sc[nt][0] - mn0);
            sc[nt][1] = __expf(sc[nt][1] - mn0);
            sc[nt][2] = __expf(sc[nt][2] - mn1);
            sc[nt][3] = __expf(sc[nt][3] - mn1);
            sum0 += sc[nt][0] + sc[nt][1];
            sum1 += sc[nt][2] + sc[nt][3];
        }
        sum0 += __shfl_xor_sync(0xffffffffu, sum0, 1);
        sum0 += __shfl_xor_sync(0xffffffffu, sum0, 2);
        sum1 += __shfl_xor_sync(0xffffffffu, sum1, 1);
        sum1 += __shfl_xor_sync(0xffffffffu, sum1, 2);
        l0 = l0 * f0 + sum0;  m0 = mn0;
        l1 = l1 * f1 + sum1;  m1 = mn1;

        // Rescale O accumulators
#pragma unroll
        for (int nt = 0; nt < 8; nt++) {
            acc[nt][0] *= f0; acc[nt][1] *= f0;
            acc[nt][2] *= f1; acc[nt][3] *= f1;
        }

        // Write P (tf32-rounded) to warp-private rows of Ps
#pragma unroll
        for (int nt = 0; nt < 8; nt++) {
            float2 p0, p1;
            p0.x = rnd_tf32(sc[nt][0]); p0.y = rnd_tf32(sc[nt][1]);
            p1.x = rnd_tf32(sc[nt][2]); p1.y = rnd_tf32(sc[nt][3]);
            *(float2*)&Ps[r0 * QK_ST + nt * 8 + tig * 2] = p0;
            *(float2*)&Ps[(r0 + 8) * QK_ST + nt * 8 + tig * 2] = p1;
        }
        __syncwarp();

        // PV: acc[nt(e)] += P[q][s] * V[s][e]
#pragma unroll
        for (int k0 = 0; k0 < 8; k0++) {
            const uint32_t* pp = (const uint32_t*)Ps + r0 * QK_ST + k0 * 8 + tig;
            uint32_t af[4];
            af[0] = pp[0];
            af[1] = pp[8 * QK_ST];
            af[2] = pp[4];
            af[3] = pp[8 * QK_ST + 4];
#pragma unroll
            for (int nt = 0; nt < 8; nt++) {
                const uint32_t* pv =
                    (const uint32_t*)Vs + (k0 * 8 + tig) * V_ST + nt * 8 + gid;
                uint32_t bf[2] = {pv[0], pv[4 * V_ST]};
                mma_tf32(acc[nt], af, bf);
            }
        }
    }

    // Epilogue: normalize, round (feeds out-proj tf32 GEMM), store
    const float inv0 = 1.f / l0, inv1 = 1.f / l1;
    float* Og = O + ((size_t)b * Lq + q0 + r0) * DHK + h * DK;
#pragma unroll
    for (int nt = 0; nt < 8; nt++) {
        const int c = nt * 8 + tig * 2;
        float2 o0, o1;
        o0.x = rnd_tf32(acc[nt][0] * inv0); o0.y = rnd_tf32(acc[nt][1] * inv0);
        o1.x = rnd_tf32(acc[nt][2] * inv1); o1.y = rnd_tf32(acc[nt][3] * inv1);
        *(float2*)(Og + c) = o0;
        *(float2*)(Og + (size_t)8 * DHK + c) = o1;
    }
}

// ===========================================================================
// Launch
// ===========================================================================
extern "C" void kernel_launch(void* const* d_in, const int* in_sizes, int n_in,
                              void* d_out, int out_size)
{
    const float* target = (const float*)d_in[0];
    const float* source = (const float*)d_in[1];
    const float* Wq = (const float*)d_in[2];
    const float* bq = (const float*)d_in[3];
    const float* Wk = (const float*)d_in[4];
    const float* bk = (const float*)d_in[5];
    const float* Wv = (const float*)d_in[6];
    const float* bv = (const float*)d_in[7];
    const float* Wo = (const float*)d_in[8];
    const float* bo = (const float*)d_in[9];
    float* out = (float*)d_out;

    float* Qb; cudaGetSymbolAddress((void**)&Qb, g_Q);
    float* Kb; cudaGetSymbolAddress((void**)&Kb, g_K);
    float* Vb; cudaGetSymbolAddress((void**)&Vb, g_V);
    float* Cb; cudaGetSymbolAddress((void**)&Cb, g_C);
    float* WT; cudaGetSymbolAddress((void**)&WT, g_WT);
    float* Sr; cudaGetSymbolAddress((void**)&Sr, g_Sr);

    const int ML = Bz * Lq;   // 16384
    const int MS = Bz * Sk;   // 8192

    cudaFuncSetAttribute(gemm_mma<0>, cudaFuncAttributeMaxDynamicSharedMemorySize, SMEM_GEMM);
    cudaFuncSetAttribute(gemm_mma<1>, cudaFuncAttributeMaxDynamicSharedMemorySize, SMEM_GEMM);
    cudaFuncSetAttribute(attn_tc, cudaFuncAttributeMaxDynamicSharedMemorySize, ATTN_SMEM);

    // Round inputs to tf32 once
    {
        const int nt4 = ML * DM / 4;        // 4M
        round_tf32_k<<<nt4 / 256, 256>>>((const float4*)target, (float4*)Cb, nt4);
        const int ns4 = MS * DLLM / 4;      // 8M
        round_tf32_k<<<ns4 / 256, 256>>>((const float4*)source, (float4*)Sr, ns4);
    }

    // Q = round(target) @ Wq + bq  (rounded output)
    transpose_k<<<dim3(DHK / 32, DM / 32), dim3(32, 8)>>>(Wq, WT, DM, DHK);
    gemm_mma<1><<<dim3(DHK / GN, ML / GM), 256, SMEM_GEMM>>>(Cb, WT, bq, Qb, DM, DHK);

    // K = round(source) @ Wk + bk
    transpose_k<<<dim3(DHK / 32, DLLM / 32), dim3(32, 8)>>>(Wk, WT, DLLM, DHK);
    gemm_mma<1><<<dim3(DHK / GN, MS / GM), 256, SMEM_GEMM>>>(Sr, WT, bk, Kb, DLLM, DHK);

    // V = round(source) @ Wv + bv
    transpose_k<<<dim3(DHK / 32, DLLM / 32), dim3(32, 8)>>>(Wv, WT, DLLM, DHK);
    gemm_mma<1><<<dim3(DHK / GN, MS / GM), 256, SMEM_GEMM>>>(Sr, WT, bv, Vb, DLLM, DHK);

    // Attention (overwrites Cb; rounded output)
    attn_tc<<<dim3(Lq / 64, NH, Bz), 128, ATTN_SMEM>>>(Qb, Kb, Vb, Cb);

    // out = C @ Wo + bo  (final output: NOT rounded)
    transpose_k<<<dim3(DLLM / 32, DHK / 32), dim3(32, 8)>>>(Wo, WT, DHK, DLLM);
    gemm_mma<0><<<dim3(DLLM / GN, ML / GM), 256, SMEM_GEMM>>>(Cb, WT, bo, out, DHK, DLLM);
}

// round 9
// speedup vs baseline: 3.8010x; 1.0878x over previous
#include <cuda_runtime.h>
#include <cstdint>
#include <math.h>

#define Bz 8
#define Lq 2048
#define Sk 1024
#define DM 1024
#define DLLM 4096
#define NH 16
#define DK 64
#define DHK 1024

// Scratch (allocation-free rule: __device__ globals)
__device__ float g_Q[(size_t)Bz * Lq * DHK];    // 64 MB
__device__ float g_K[(size_t)Bz * Sk * DHK];    // 32 MB
__device__ float g_V[(size_t)Bz * Sk * DHK];    // 32 MB
__device__ float g_C[(size_t)Bz * Lq * DHK];    // 64 MB (perm-rounded target, then attn out)
__device__ float g_WT[(size_t)DLLM * DHK];      // 16 MB (transposed+rounded+K-permuted weight)
__device__ float g_Sr[(size_t)Bz * Sk * DLLM];  // 128 MB (perm-rounded source)

// ===========================================================================
// Helpers
// ===========================================================================
__device__ __forceinline__ uint32_t smem_u32(const void* p) {
    uint32_t a;
    asm("{ .reg .u64 t; cvta.to.shared.u64 t, %1; cvt.u32.u64 %0, t; }" : "=r"(a) : "l"(p));
    return a;
}
__device__ __forceinline__ void cp16(uint32_t dst, const void* src) {
    asm volatile("cp.async.cg.shared.global [%0], [%1], 16;" :: "r"(dst), "l"(src));
}
#define CP_COMMIT() asm volatile("cp.async.commit_group;" ::: "memory")
#define CP_WAIT0()  asm volatile("cp.async.wait_group 0;" ::: "memory")

__device__ __forceinline__ float rnd_tf32(float x) {
    uint32_t r;
    asm("cvt.rna.tf32.f32 %0, %1;" : "=r"(r) : "f"(x));
    return __uint_as_float(r);
}
// K-permutation within groups of 8: pos of original index j is p(j).
// Layout order becomes [0,4,1,5,2,6,3,7] so (k, k+4) pairs are adjacent.
__device__ __forceinline__ int kperm(int j) { return (j < 4) ? 2 * j : 2 * j - 7; }

__device__ __forceinline__ void mma_tf32(float c[4], const uint32_t a[4], const uint32_t b[2]) {
    asm volatile(
        "mma.sync.aligned.m16n8k8.row.col.f32.tf32.tf32.f32 "
        "{%0,%1,%2,%3}, {%4,%5,%6,%7}, {%8,%9}, {%0,%1,%2,%3};"
        : "+f"(c[0]), "+f"(c[1]), "+f"(c[2]), "+f"(c[3])
        : "r"(a[0]), "r"(a[1]), "r"(a[2]), "r"(a[3]), "r"(b[0]), "r"(b[1]));
}

// ===========================================================================
// Elementwise tf32 round + K-pair permutation (row stride divisible by 8,
// so flat_index & 7 == k & 7).
// ===========================================================================
__global__ __launch_bounds__(256) void round_perm_k(
    const float4* __restrict__ in, float* __restrict__ out, int n4)
{
    const int i = blockIdx.x * 256 + threadIdx.x;
    if (i < n4) {
        float4 v = in[i];
        const size_t f = (size_t)i * 4;
        float vv[4] = {rnd_tf32(v.x), rnd_tf32(v.y), rnd_tf32(v.z), rnd_tf32(v.w)};
#pragma unroll
        for (int j = 0; j < 4; j++) {
            const size_t fj = f + j;
            const int k7 = (int)(fj & 7);
            out[fj - k7 + kperm(k7)] = vv[j];
        }
    }
}

// ===========================================================================
// Weight transpose + tf32 round + K-pair permutation on output column
// (output col = original row r = GEMM K-dim): in [R,C] -> out [C,R].
// ===========================================================================
__global__ __launch_bounds__(256) void transpose_k(
    const float* __restrict__ in, float* __restrict__ out, int R, int C)
{
    __shared__ float tile[32][33];
    const int c0 = blockIdx.x * 32, r0 = blockIdx.y * 32;
    const int x = threadIdx.x, y = threadIdx.y;  // 32 x 8
#pragma unroll
    for (int i = 0; i < 32; i += 8)
        tile[y + i][x] = in[(size_t)(r0 + y + i) * C + c0 + x];
    __syncthreads();
    const int xp = (x & ~7) + kperm(x & 7);
#pragma unroll
    for (int i = 0; i < 32; i += 8)
        out[(size_t)(c0 + y + i) * R + r0 + xp] = rnd_tf32(tile[x][y + i]);
}

// ===========================================================================
// tf32 mma.sync GEMM: C[M,N] = A[M,K] @ Bt[N,K]^T + bias
// A and Bt have K pre-permuted in pair order -> fragment loads are LDS.64.
// 128x128x32 block tile, 8 warps (2M x 4N), m16n8k8, double-buffered cp.async,
// one barrier per mainloop iteration.
// ===========================================================================
#define GM 128
#define GN 128
#define GKC 32
#define TST 40                                   // 40 % 32 == 8: LDS.64 conflict-free
#define STAGE_FLOATS (2 * 128 * TST)             // 10240
#define SMEM_GEMM (2 * STAGE_FLOATS * 4)         // 81920 bytes

template <int RND>
__global__ __launch_bounds__(256, 2) void gemm_mma(
    const float* __restrict__ A, const float* __restrict__ Bt,
    const float* __restrict__ bias, float* __restrict__ C,
    int K, int N)
{
    extern __shared__ float smf[];
    const uint32_t smem_base = smem_u32(smf);
    const int tid  = threadIdx.x;
    const int wid  = tid >> 5;
    const int lane = tid & 31;
    const int wm   = wid >> 2;
    const int wn   = wid & 3;
    const int gid  = lane >> 2;
    const int tig  = lane & 3;
    const int m0 = blockIdx.y * GM;
    const int n0 = blockIdx.x * GN;

    const float* Ag = A + (size_t)m0 * K;
    const float* Bg = Bt + (size_t)n0 * K;

    auto issue_stage = [&](int i) {
        const int k0 = i * GKC;
        const uint32_t sb = smem_base + (uint32_t)((i & 1) * STAGE_FLOATS * 4);
#pragma unroll
        for (int u = 0; u < 4; u++) {
            const int g = tid + u * 256;
            const int row = g >> 3, c4 = g & 7;
            cp16(sb + (uint32_t)(row * TST * 4 + c4 * 16),
                 Ag + (size_t)row * K + k0 + c4 * 4);
        }
        const uint32_t sbB = sb + 128 * TST * 4;
#pragma unroll
        for (int u = 0; u < 4; u++) {
            const int g = tid + u * 256;
            const int row = g >> 3, c4 = g & 7;
            cp16(sbB + (uint32_t)(row * TST * 4 + c4 * 16),
                 Bg + (size_t)row * K + k0 + c4 * 4);
        }
        CP_COMMIT();
    };

    float acc[4][4][4];
#pragma unroll
    for (int mt = 0; mt < 4; mt++)
#pragma unroll
        for (int nt = 0; nt < 4; nt++)
#pragma unroll
            for (int r = 0; r < 4; r++) acc[mt][nt][r] = 0.f;

    const int niter = K / GKC;
    issue_stage(0);

    for (int i = 0; i < niter; i++) {
        CP_WAIT0();
        __syncthreads();   // stage i visible to all; also fences reads of buffer (i&1)
                           // from iteration i-2 before issue below overwrites it
        if (i + 1 < niter) issue_stage(i + 1);

        const uint32_t* As = (const uint32_t*)(smf + (i & 1) * STAGE_FLOATS);
        const uint32_t* Bs = As + 128 * TST;

#pragma unroll
        for (int ks = 0; ks < 4; ks++) {
            uint32_t af[4][4];
#pragma unroll
            for (int mt = 0; mt < 4; mt++) {
                const uint32_t* pa = As + (wm * 64 + mt * 16 + gid) * TST + ks * 8 + tig * 2;
                const uint2 lo = *(const uint2*)pa;            // k=tig, k=tig+4 (row)
                const uint2 hi = *(const uint2*)(pa + 8 * TST);// same, row+8
                af[mt][0] = lo.x; af[mt][1] = hi.x;
                af[mt][2] = lo.y; af[mt][3] = hi.y;
            }
            uint32_t bf[4][2];
#pragma unroll
            for (int nt = 0; nt < 4; nt++) {
                const uint32_t* pb = Bs + (wn * 32 + nt * 8 + gid) * TST + ks * 8 + tig * 2;
                const uint2 b = *(const uint2*)pb;
                bf[nt][0] = b.x; bf[nt][1] = b.y;
            }
#pragma unroll
            for (int mt = 0; mt < 4; mt++)
#pragma unroll
                for (int nt = 0; nt < 4; nt++)
                    mma_tf32(acc[mt][nt], af[mt], bf[nt]);
        }
        // no trailing barrier: next iteration's wait+barrier protects the buffer
    }

#pragma unroll
    for (int mt = 0; mt < 4; mt++) {
        const int r = m0 + wm * 64 + mt * 16 + gid;
#pragma unroll
        for (int nt = 0; nt < 4; nt++) {
            const int c = n0 + wn * 32 + nt * 8 + tig * 2;
            const float bx = bias[c], by = bias[c + 1];
            float2 o0, o1;
            o0.x = acc[mt][nt][0] + bx; o0.y = acc[mt][nt][1] + by;
            o1.x = acc[mt][nt][2] + bx; o1.y = acc[mt][nt][3] + by;
            if (RND) {
                o0.x = rnd_tf32(o0.x); o0.y = rnd_tf32(o0.y);
                o1.x = rnd_tf32(o1.x); o1.y = rnd_tf32(o1.y);
            }
            *(float2*)(C + (size_t)r * N + c) = o0;
            *(float2*)(C + (size_t)(r + 8) * N + c) = o1;
        }
    }
}

// ===========================================================================
// Tensor-core flash attention (tf32 mma.sync).  Q/K/V in NATURAL layout.
// Output written with K-pair-permuted columns (feeds the out-proj GEMM).
// Grid (L/64, H, B), 128 threads (4 warps).
// ===========================================================================
#define QK_ST 68
#define V_ST  72
#define ATTN_SMEM ((2 * 64 * QK_ST + 64 * V_ST) * 4)   // 53248 bytes

__global__ __launch_bounds__(128) void attn_tc(
    const float* __restrict__ Q, const float* __restrict__ K,
    const float* __restrict__ V, float* __restrict__ O)
{
    extern __shared__ float sm[];
    float* Qs = sm;                        // [64][QK_ST]
    float* Ks = Qs + 64 * QK_ST;           // [64][QK_ST]
    float* Vs = Ks + 64 * QK_ST;           // [64][V_ST]
    float* Ps = Qs;                        // alias (Q is register-resident in loop)

    const int tid  = threadIdx.x;
    const int wid  = tid >> 5;
    const int lane = tid & 31;
    const int gid  = lane >> 2;
    const int tig  = lane & 3;
    const int q0 = blockIdx.x * 64;
    const int h  = blockIdx.y;
    const int b  = blockIdx.z;

    const float* Qg = Q + ((size_t)b * Lq + q0) * DHK + h * DK;
    const float* Kg = K + ((size_t)b * Sk) * DHK + h * DK;
    const float* Vg = V + ((size_t)b * Sk) * DHK + h * DK;

    for (int g = tid; g < 64 * 16; g += 128) {
        const int r = g >> 4, e4 = g & 15;
        float4 v = *(const float4*)(Qg + (size_t)r * DHK + e4 * 4);
        *(float4*)&Qs[r * QK_ST + e4 * 4] = v;
    }
    __syncthreads();

    const int r0 = wid * 16 + gid;
    uint32_t qf[8][4];
#pragma unroll
    for (int k0 = 0; k0 < 8; k0++) {
        qf[k0][0] = __float_as_uint(Qs[r0 * QK_ST + k0 * 8 + tig] * 0.125f);
        qf[k0][1] = __float_as_uint(Qs[(r0 + 8) * QK_ST + k0 * 8 + tig] * 0.125f);
        qf[k0][2] = __float_as_uint(Qs[r0 * QK_ST + k0 * 8 + tig + 4] * 0.125f);
        qf[k0][3] = __float_as_uint(Qs[(r0 + 8) * QK_ST + k0 * 8 + tig + 4] * 0.125f);
    }

    float m0 = -INFINITY, m1 = -INFINITY, l0 = 0.f, l1 = 0.f;
    float acc[8][4];
#pragma unroll
    for (int nt = 0; nt < 8; nt++)
#pragma unroll
        for (int r = 0; r < 4; r++) acc[nt][r] = 0.f;

    for (int s0 = 0; s0 < Sk; s0 += 64) {
        __syncthreads();
        for (int g = tid; g < 64 * 16; g += 128) {
            const int r = g >> 4, e4 = g & 15;
            float4 kv = *(const float4*)(Kg + (size_t)(s0 + r) * DHK + e4 * 4);
            *(float4*)&Ks[r * QK_ST + e4 * 4] = kv;
            float4 vv = *(const float4*)(Vg + (size_t)(s0 + r) * DHK + e4 * 4);
            *(float4*)&Vs[r * V_ST + e4 * 4] = vv;
        }
        __syncthreads();

        float sc[8][4];
#pragma unroll
        for (int nt = 0; nt < 8; nt++)
#pragma unroll
            for (int r = 0; r < 4; r++) sc[nt][r] = 0.f;
#pragma unroll
        for (int k0 = 0; k0 < 8; k0++) {
#pragma unroll
            for (int nt = 0; nt < 8; nt++) {
                const uint32_t* pk =
                    (const uint32_t*)Ks + (nt * 8 + gid) * QK_ST + k0 * 8 + tig;
                uint32_t bf[2] = {pk[0], pk[4]};
                mma_tf32(sc[nt], qf[k0], bf);
            }
        }

        float mx0 = -INFINITY, mx1 = -INFINITY;
#pragma unroll
        for (int nt = 0; nt < 8; nt++) {
            mx0 = fmaxf(mx0, fmaxf(sc[nt][0], sc[nt][1]));
            mx1 = fmaxf(mx1, fmaxf(sc[nt][2], sc[nt][3]));
        }
        mx0 = fmaxf(mx0, __shfl_xor_sync(0xffffffffu, mx0, 1));
        mx0 = fmaxf(mx0, __shfl_xor_sync(0xffffffffu, mx0, 2));
        mx1 = fmaxf(mx1, __shfl_xor_sync(0xffffffffu, mx1, 1));
        mx1 = fmaxf(mx1, __shfl_xor_sync(0xffffffffu, mx1, 2));
        const float mn0 = fmaxf(m0, mx0), mn1 = fmaxf(m1, mx1);
        const float f0 = __expf(m0 - mn0), f1 = __expf(m1 - mn1);
        float sum0 = 0.f, sum1 = 0.f;
#pragma unroll
        for (int nt = 0; nt < 8; nt++) {
            sc[nt][0] = __expf(sc[nt][0] - mn0);
            sc[nt][1] = __expf(sc[nt][1] - mn0);
            sc[nt][2] = __expf(sc[nt][2] - mn1);
            sc[nt][3] = __expf(sc[nt][3] - mn1);
            sum0 += sc[nt][0] + sc[nt][1];
            sum1 += sc[nt][2] + sc[nt][3];
        }
        sum0 += __shfl_xor_sync(0xffffffffu, sum0, 1);
        sum0 += __shfl_xor_sync(0xffffffffu, sum0, 2);
        sum1 += __shfl_xor_sync(0xffffffffu, sum1, 1);
        sum1 += __shfl_xor_sync(0xffffffffu, sum1, 2);
        l0 = l0 * f0 + sum0;  m0 = mn0;
        l1 = l1 * f1 + sum1;  m1 = mn1;

#pragma unroll
        for (int nt = 0; nt < 8; nt++) {
            acc[nt][0] *= f0; acc[nt][1] *= f0;
            acc[nt][2] *= f1; acc[nt][3] *= f1;
        }

#pragma unroll
        for (int nt = 0; nt < 8; nt++) {
            float2 p0, p1;
            p0.x = rnd_tf32(sc[nt][0]); p0.y = rnd_tf32(sc[nt][1]);
            p1.x = rnd_tf32(sc[nt][2]); p1.y = rnd_tf32(sc[nt][3]);
            *(float2*)&Ps[r0 * QK_ST + nt * 8 + tig * 2] = p0;
            *(float2*)&Ps[(r0 + 8) * QK_ST + nt * 8 + tig * 2] = p1;
        }
        __syncwarp();

#pragma unroll
        for (int k0 = 0; k0 < 8; k0++) {
            const uint32_t* pp = (const uint32_t*)Ps + r0 * QK_ST + k0 * 8 + tig;
            uint32_t af[4];
            af[0] = pp[0];
            af[1] = pp[8 * QK_ST];
            af[2] = pp[4];
            af[3] = pp[8 * QK_ST + 4];
#pragma unroll
            for (int nt = 0; nt < 8; nt++) {
                const uint32_t* pv =
                    (const uint32_t*)Vs + (k0 * 8 + tig) * V_ST + nt * 8 + gid;
                uint32_t bf[2] = {pv[0], pv[4 * V_ST]};
                mma_tf32(acc[nt], af, bf);
            }
        }
    }

    // Epilogue: normalize, round, store with K-pair-permuted columns
    // (this tensor is the A operand / K-dim of the out-proj GEMM).
    const float inv0 = 1.f / l0, inv1 = 1.f / l1;
    float* Og = O + ((size_t)b * Lq + q0 + r0) * DHK + h * DK;
    const int cpa = kperm(2 * tig);       // permuted position of col 2*tig
    const int cpb = kperm(2 * tig + 1);   // permuted position of col 2*tig+1
#pragma unroll
    for (int nt = 0; nt < 8; nt++) {
        Og[nt * 8 + cpa] = rnd_tf32(acc[nt][0] * inv0);
        Og[nt * 8 + cpb] = rnd_tf32(acc[nt][1] * inv0);
        Og[(size_t)8 * DHK + nt * 8 + cpa] = rnd_tf32(acc[nt][2] * inv1);
        Og[(size_t)8 * DHK + nt * 8 + cpb] = rnd_tf32(acc[nt][3] * inv1);
    }
}

// ===========================================================================
// Launch
// ===========================================================================
extern "C" void kernel_launch(void* const* d_in, const int* in_sizes, int n_in,
                              void* d_out, int out_size)
{
    const float* target = (const float*)d_in[0];
    const float* source = (const float*)d_in[1];
    const float* Wq = (const float*)d_in[2];
    const float* bq = (const float*)d_in[3];
    const float* Wk = (const float*)d_in[4];
    const float* bk = (const float*)d_in[5];
    const float* Wv = (const float*)d_in[6];
    const float* bv = (const float*)d_in[7];
    const float* Wo = (const float*)d_in[8];
    const float* bo = (const float*)d_in[9];
    float* out = (float*)d_out;

    float* Qb; cudaGetSymbolAddress((void**)&Qb, g_Q);
    float* Kb; cudaGetSymbolAddress((void**)&Kb, g_K);
    float* Vb; cudaGetSymbolAddress((void**)&Vb, g_V);
    float* Cb; cudaGetSymbolAddress((void**)&Cb, g_C);
    float* WT; cudaGetSymbolAddress((void**)&WT, g_WT);
    float* Sr; cudaGetSymbolAddress((void**)&Sr, g_Sr);

    const int ML = Bz * Lq;   // 16384
    const int MS = Bz * Sk;   // 8192

    cudaFuncSetAttribute(gemm_mma<0>, cudaFuncAttributeMaxDynamicSharedMemorySize, SMEM_GEMM);
    cudaFuncSetAttribute(gemm_mma<1>, cudaFuncAttributeMaxDynamicSharedMemorySize, SMEM_GEMM);
    cudaFuncSetAttribute(attn_tc, cudaFuncAttributeMaxDynamicSharedMemorySize, ATTN_SMEM);

    // Round + K-permute inputs once
    {
        const int nt4 = ML * DM / 4;        // 4M
        round_perm_k<<<nt4 / 256, 256>>>((const float4*)target, Cb, nt4);
        const int ns4 = MS * DLLM / 4;      // 8M
        round_perm_k<<<ns4 / 256, 256>>>((const float4*)source, Sr, ns4);
    }

    // Q = round(target) @ Wq + bq  (rounded natural-N output)
    transpose_k<<<dim3(DHK / 32, DM / 32), dim3(32, 8)>>>(Wq, WT, DM, DHK);
    gemm_mma<1><<<dim3(DHK / GN, ML / GM), 256, SMEM_GEMM>>>(Cb, WT, bq, Qb, DM, DHK);

    // K = round(source) @ Wk + bk
    transpose_k<<<dim3(DHK / 32, DLLM / 32), dim3(32, 8)>>>(Wk, WT, DLLM, DHK);
    gemm_mma<1><<<dim3(DHK / GN, MS / GM), 256, SMEM_GEMM>>>(Sr, WT, bk, Kb, DLLM, DHK);

    // V = round(source) @ Wv + bv
    transpose_k<<<dim3(DHK / 32, DLLM / 32), dim3(32, 8)>>>(Wv, WT, DLLM, DHK);
    gemm_mma<1><<<dim3(DHK / GN, MS / GM), 256, SMEM_GEMM>>>(Sr, WT, bv, Vb, DLLM, DHK);

    // Attention (overwrites Cb; output rounded + K-permuted for out-proj)
    attn_tc<<<dim3(Lq / 64, NH, Bz), 128, ATTN_SMEM>>>(Qb, Kb, Vb, Cb);

    // out = C @ Wo + bo  (final output: natural, NOT rounded)
    transpose_k<<<dim3(DLLM / 32, DHK / 32), dim3(32, 8)>>>(Wo, WT, DHK, DLLM);
    gemm_mma<0><<<dim3(DLLM / GN, ML / GM), 256, SMEM_GEMM>>>(Cb, WT, bo, out, DHK, DLLM);
}